// round 3
// baseline (speedup 1.0000x reference)
#include <cuda_runtime.h>

// MassSprings energy: E = 0.5 * sum_e k[e] * (||x[i1]-x[i2]|| - l0[e])^2
// Inputs (metadata order): x [100000*3 f32], l0 [6.4M f32], k [6.4M f32],
//                          indices [6.4M*2 i32]. Output: 1 f32 scalar.
// Strategy: DRAM-bound stream of indices/l0/k (102.4 MB compulsory);
// x (1.2 MB) gathers are L2-resident. Vectorized 4-edges-per-iter grid-stride,
// warp+block reduction, one float atomicAdd per block.

#define EPS 1e-6f

__global__ void ms_init_out(float* out) {
    if (threadIdx.x == 0) out[0] = 0.0f;
}

__device__ __forceinline__ float edge_energy(const float* __restrict__ x,
                                             int i, int j, float L, float K) {
    float ax = __ldg(x + 3 * i);
    float ay = __ldg(x + 3 * i + 1);
    float az = __ldg(x + 3 * i + 2);
    float bx = __ldg(x + 3 * j);
    float by = __ldg(x + 3 * j + 1);
    float bz = __ldg(x + 3 * j + 2);
    float dx = ax - bx;
    float dy = ay - by;
    float dz = az - bz;
    float q  = fmaf(dx, dx, fmaf(dy, dy, dz * dz));
    float l  = sqrtf(q + EPS);
    float dl = l - L;
    return K * dl * dl;
}

__global__ void __launch_bounds__(256)
ms_energy_kernel(const float*  __restrict__ x,
                 const float*  __restrict__ l0,
                 const float*  __restrict__ kk,
                 const int*    __restrict__ indices,   // [E,2] interleaved
                 float*        __restrict__ out,
                 int E)
{
    const int tid    = blockIdx.x * blockDim.x + threadIdx.x;
    const int stride = gridDim.x * blockDim.x;

    const int E4 = E >> 2;  // groups of 4 edges
    const int4*   idx4 = reinterpret_cast<const int4*>(indices); // 2 edges / int4
    const float4* l04  = reinterpret_cast<const float4*>(l0);
    const float4* k4   = reinterpret_cast<const float4*>(kk);

    float acc = 0.0f;

    for (int g = tid; g < E4; g += stride) {
        int4   a = __ldg(&idx4[2 * g]);       // edges 4g, 4g+1
        int4   b = __ldg(&idx4[2 * g + 1]);   // edges 4g+2, 4g+3
        float4 L = __ldg(&l04[g]);
        float4 K = __ldg(&k4[g]);
        acc += edge_energy(x, a.x, a.y, L.x, K.x);
        acc += edge_energy(x, a.z, a.w, L.y, K.y);
        acc += edge_energy(x, b.x, b.y, L.z, K.z);
        acc += edge_energy(x, b.z, b.w, L.w, K.w);
    }

    // tail (E not multiple of 4)
    for (int e = (E4 << 2) + tid; e < E; e += stride) {
        int i = __ldg(indices + 2 * e);
        int j = __ldg(indices + 2 * e + 1);
        acc += edge_energy(x, i, j, __ldg(l0 + e), __ldg(kk + e));
    }

    // warp reduce
    #pragma unroll
    for (int o = 16; o > 0; o >>= 1)
        acc += __shfl_xor_sync(0xFFFFFFFFu, acc, o);

    __shared__ float wsum[8];
    const int lane = threadIdx.x & 31;
    const int wid  = threadIdx.x >> 5;
    if (lane == 0) wsum[wid] = acc;
    __syncthreads();

    if (wid == 0) {
        float v = (lane < (blockDim.x >> 5)) ? wsum[lane] : 0.0f;
        #pragma unroll
        for (int o = 4; o > 0; o >>= 1)
            v += __shfl_xor_sync(0xFFFFFFFFu, v, o);
        if (lane == 0)
            atomicAdd(out, 0.5f * v);
    }
}

extern "C" void kernel_launch(void* const* d_in, const int* in_sizes, int n_in,
                              void* d_out, int out_size) {
    const float* x       = (const float*)d_in[0];   // [V*3]
    const float* l0      = (const float*)d_in[1];   // [E]
    const float* kk      = (const float*)d_in[2];   // [E]
    const int*   indices = (const int*)  d_in[3];   // [E*2]
    float*       out     = (float*)d_out;

    const int E = in_sizes[1];

    ms_init_out<<<1, 32>>>(out);

    const int threads = 256;
    const int blocks  = 148 * 8;   // one fat wave across the chip
    ms_energy_kernel<<<blocks, threads>>>(x, l0, kk, indices, out, E);
}

// round 4
// speedup vs baseline: 1.3005x; 1.3005x over previous
#include <cuda_runtime.h>

// MassSprings energy: E = 0.5 * sum_e k[e] * (||x[i1]-x[i2]|| - l0[e])^2
// R3: pack x into float4 scratch so each vertex gather is 1x LDG.128 (was
// 3x LDG.32) -> 3x fewer L1tex requests (R2 showed L1=73% bound).
// Streamed arrays use __ldcs (evict-first) to keep L1 for x gathers.

#define EPS 1e-6f
#define NV_MAX 100000

__device__ float4 g_xpad[NV_MAX];

__global__ void ms_init_out(float* out) {
    if (threadIdx.x == 0) out[0] = 0.0f;
}

__global__ void __launch_bounds__(256)
ms_pack_x(const float* __restrict__ x, int V) {
    int v = blockIdx.x * blockDim.x + threadIdx.x;
    if (v < V) {
        float4 p;
        p.x = x[3 * v];
        p.y = x[3 * v + 1];
        p.z = x[3 * v + 2];
        p.w = 0.0f;
        g_xpad[v] = p;
    }
}

__device__ __forceinline__ float edge_energy4(int i, int j, float L, float K) {
    float4 a = __ldg(&g_xpad[i]);
    float4 b = __ldg(&g_xpad[j]);
    float dx = a.x - b.x;
    float dy = a.y - b.y;
    float dz = a.z - b.z;
    float q  = fmaf(dx, dx, fmaf(dy, dy, dz * dz));
    float l  = sqrtf(q + EPS);
    float dl = l - L;
    return K * dl * dl;
}

__global__ void __launch_bounds__(256)
ms_energy_kernel(const float*  __restrict__ l0,
                 const float*  __restrict__ kk,
                 const int*    __restrict__ indices,   // [E,2] interleaved
                 float*        __restrict__ out,
                 int E)
{
    const int tid    = blockIdx.x * blockDim.x + threadIdx.x;
    const int stride = gridDim.x * blockDim.x;

    const int E4 = E >> 2;
    const int4*   idx4 = reinterpret_cast<const int4*>(indices); // 2 edges / int4
    const float4* l04  = reinterpret_cast<const float4*>(l0);
    const float4* k4   = reinterpret_cast<const float4*>(kk);

    float acc = 0.0f;

    for (int g = tid; g < E4; g += stride) {
        // streamed (evict-first: don't pollute L1, x lives there)
        int4   a = __ldcs(&idx4[2 * g]);       // edges 4g, 4g+1
        int4   b = __ldcs(&idx4[2 * g + 1]);   // edges 4g+2, 4g+3
        float4 L = __ldcs(&l04[g]);
        float4 K = __ldcs(&k4[g]);

        // batch all 8 gathers before the math (MLP)
        float4 p0 = __ldg(&g_xpad[a.x]);
        float4 q0 = __ldg(&g_xpad[a.y]);
        float4 p1 = __ldg(&g_xpad[a.z]);
        float4 q1 = __ldg(&g_xpad[a.w]);
        float4 p2 = __ldg(&g_xpad[b.x]);
        float4 q2 = __ldg(&g_xpad[b.y]);
        float4 p3 = __ldg(&g_xpad[b.z]);
        float4 q3 = __ldg(&g_xpad[b.w]);

        float dx, dy, dz, qd, l, dl;

        dx = p0.x - q0.x; dy = p0.y - q0.y; dz = p0.z - q0.z;
        qd = fmaf(dx, dx, fmaf(dy, dy, dz * dz));
        l  = sqrtf(qd + EPS); dl = l - L.x;
        acc = fmaf(K.x * dl, dl, acc);

        dx = p1.x - q1.x; dy = p1.y - q1.y; dz = p1.z - q1.z;
        qd = fmaf(dx, dx, fmaf(dy, dy, dz * dz));
        l  = sqrtf(qd + EPS); dl = l - L.y;
        acc = fmaf(K.y * dl, dl, acc);

        dx = p2.x - q2.x; dy = p2.y - q2.y; dz = p2.z - q2.z;
        qd = fmaf(dx, dx, fmaf(dy, dy, dz * dz));
        l  = sqrtf(qd + EPS); dl = l - L.z;
        acc = fmaf(K.z * dl, dl, acc);

        dx = p3.x - q3.x; dy = p3.y - q3.y; dz = p3.z - q3.z;
        qd = fmaf(dx, dx, fmaf(dy, dy, dz * dz));
        l  = sqrtf(qd + EPS); dl = l - L.w;
        acc = fmaf(K.w * dl, dl, acc);
    }

    // tail (E not multiple of 4)
    for (int e = (E4 << 2) + tid; e < E; e += stride) {
        int i = __ldg(indices + 2 * e);
        int j = __ldg(indices + 2 * e + 1);
        acc += edge_energy4(i, j, __ldg(l0 + e), __ldg(kk + e));
    }

    // warp reduce
    #pragma unroll
    for (int o = 16; o > 0; o >>= 1)
        acc += __shfl_xor_sync(0xFFFFFFFFu, acc, o);

    __shared__ float wsum[8];
    const int lane = threadIdx.x & 31;
    const int wid  = threadIdx.x >> 5;
    if (lane == 0) wsum[wid] = acc;
    __syncthreads();

    if (wid == 0) {
        float v = (lane < (blockDim.x >> 5)) ? wsum[lane] : 0.0f;
        #pragma unroll
        for (int o = 4; o > 0; o >>= 1)
            v += __shfl_xor_sync(0xFFFFFFFFu, v, o);
        if (lane == 0)
            atomicAdd(out, 0.5f * v);
    }
}

extern "C" void kernel_launch(void* const* d_in, const int* in_sizes, int n_in,
                              void* d_out, int out_size) {
    const float* x       = (const float*)d_in[0];   // [V*3]
    const float* l0      = (const float*)d_in[1];   // [E]
    const float* kk      = (const float*)d_in[2];   // [E]
    const int*   indices = (const int*)  d_in[3];   // [E*2]
    float*       out     = (float*)d_out;

    const int E = in_sizes[1];
    int V = in_sizes[0] / 3;
    if (V > NV_MAX) V = NV_MAX;

    ms_init_out<<<1, 32>>>(out);
    ms_pack_x<<<(V + 255) / 256, 256>>>(x, V);

    const int threads = 256;
    const int blocks  = 148 * 8;
    ms_energy_kernel<<<blocks, threads>>>(l0, kk, indices, out, E);
}

// round 5
// speedup vs baseline: 1.4434x; 1.1098x over previous
#include <cuda_runtime.h>

// MassSprings energy: E = 0.5 * sum_e k[e] * (||x[i1]-x[i2]|| - l0[e])^2
// R4: fold out-zeroing into pack kernel (kills the 3.4us ms_init_out launch),
// unroll main loop x2 for deeper gather MLP. Bound: L1tex wavefronts
// (~2 wf/edge, one per random 128B line touched) — near algorithmic floor.

#define EPS 1e-6f
#define NV_MAX 100000

__device__ float4 g_xpad[NV_MAX];

__global__ void __launch_bounds__(512)
ms_pack_x(const float* __restrict__ x, float* __restrict__ out, int V) {
    int v = blockIdx.x * blockDim.x + threadIdx.x;
    if (v == 0) out[0] = 0.0f;               // folded init (out poisoned 0xAA)
    if (v < V) {
        float4 p;
        p.x = __ldg(x + 3 * v);
        p.y = __ldg(x + 3 * v + 1);
        p.z = __ldg(x + 3 * v + 2);
        p.w = 0.0f;
        g_xpad[v] = p;
    }
}

__device__ __forceinline__ float edge_energy4(int i, int j, float L, float K) {
    float4 a = __ldg(&g_xpad[i]);
    float4 b = __ldg(&g_xpad[j]);
    float dx = a.x - b.x;
    float dy = a.y - b.y;
    float dz = a.z - b.z;
    float q  = fmaf(dx, dx, fmaf(dy, dy, dz * dz));
    float l  = sqrtf(q + EPS);
    float dl = l - L;
    return K * dl * dl;
}

__global__ void __launch_bounds__(256)
ms_energy_kernel(const float*  __restrict__ l0,
                 const float*  __restrict__ kk,
                 const int*    __restrict__ indices,   // [E,2] interleaved
                 float*        __restrict__ out,
                 int E)
{
    const int tid    = blockIdx.x * blockDim.x + threadIdx.x;
    const int stride = gridDim.x * blockDim.x;

    const int E4 = E >> 2;
    const int4*   idx4 = reinterpret_cast<const int4*>(indices); // 2 edges / int4
    const float4* l04  = reinterpret_cast<const float4*>(l0);
    const float4* k4   = reinterpret_cast<const float4*>(kk);

    float acc = 0.0f;

    #pragma unroll 2
    for (int g = tid; g < E4; g += stride) {
        // streamed, evict-first (keep L1 for x gathers)
        int4   a = __ldcs(&idx4[2 * g]);       // edges 4g, 4g+1
        int4   b = __ldcs(&idx4[2 * g + 1]);   // edges 4g+2, 4g+3
        float4 L = __ldcs(&l04[g]);
        float4 K = __ldcs(&k4[g]);

        // batch all 8 gathers before any math (MLP)
        float4 p0 = __ldg(&g_xpad[a.x]);
        float4 q0 = __ldg(&g_xpad[a.y]);
        float4 p1 = __ldg(&g_xpad[a.z]);
        float4 q1 = __ldg(&g_xpad[a.w]);
        float4 p2 = __ldg(&g_xpad[b.x]);
        float4 q2 = __ldg(&g_xpad[b.y]);
        float4 p3 = __ldg(&g_xpad[b.z]);
        float4 q3 = __ldg(&g_xpad[b.w]);

        float dx, dy, dz, qd, l, dl;

        dx = p0.x - q0.x; dy = p0.y - q0.y; dz = p0.z - q0.z;
        qd = fmaf(dx, dx, fmaf(dy, dy, dz * dz));
        l  = sqrtf(qd + EPS); dl = l - L.x;
        acc = fmaf(K.x * dl, dl, acc);

        dx = p1.x - q1.x; dy = p1.y - q1.y; dz = p1.z - q1.z;
        qd = fmaf(dx, dx, fmaf(dy, dy, dz * dz));
        l  = sqrtf(qd + EPS); dl = l - L.y;
        acc = fmaf(K.y * dl, dl, acc);

        dx = p2.x - q2.x; dy = p2.y - q2.y; dz = p2.z - q2.z;
        qd = fmaf(dx, dx, fmaf(dy, dy, dz * dz));
        l  = sqrtf(qd + EPS); dl = l - L.z;
        acc = fmaf(K.z * dl, dl, acc);

        dx = p3.x - q3.x; dy = p3.y - q3.y; dz = p3.z - q3.z;
        qd = fmaf(dx, dx, fmaf(dy, dy, dz * dz));
        l  = sqrtf(qd + EPS); dl = l - L.w;
        acc = fmaf(K.w * dl, dl, acc);
    }

    // tail (E not multiple of 4)
    for (int e = (E4 << 2) + tid; e < E; e += stride) {
        int i = __ldg(indices + 2 * e);
        int j = __ldg(indices + 2 * e + 1);
        acc += edge_energy4(i, j, __ldg(l0 + e), __ldg(kk + e));
    }

    // warp reduce
    #pragma unroll
    for (int o = 16; o > 0; o >>= 1)
        acc += __shfl_xor_sync(0xFFFFFFFFu, acc, o);

    __shared__ float wsum[8];
    const int lane = threadIdx.x & 31;
    const int wid  = threadIdx.x >> 5;
    if (lane == 0) wsum[wid] = acc;
    __syncthreads();

    if (wid == 0) {
        float v = (lane < (blockDim.x >> 5)) ? wsum[lane] : 0.0f;
        #pragma unroll
        for (int o = 4; o > 0; o >>= 1)
            v += __shfl_xor_sync(0xFFFFFFFFu, v, o);
        if (lane == 0)
            atomicAdd(out, 0.5f * v);
    }
}

extern "C" void kernel_launch(void* const* d_in, const int* in_sizes, int n_in,
                              void* d_out, int out_size) {
    const float* x       = (const float*)d_in[0];   // [V*3]
    const float* l0      = (const float*)d_in[1];   // [E]
    const float* kk      = (const float*)d_in[2];   // [E]
    const int*   indices = (const int*)  d_in[3];   // [E*2]
    float*       out     = (float*)d_out;

    const int E = in_sizes[1];
    int V = in_sizes[0] / 3;
    if (V > NV_MAX) V = NV_MAX;

    ms_pack_x<<<(V + 511) / 512, 512>>>(x, out, V);

    const int threads = 256;
    const int blocks  = 148 * 8;
    ms_energy_kernel<<<blocks, threads>>>(l0, kk, indices, out, E);
}